// round 1
// baseline (speedup 1.0000x reference)
#include <cuda_runtime.h>
#include <cuda_bf16.h>
#include <math_constants.h>

// Problem constants
#define BATCH 16
#define CIN   512
#define COUT  512
#define HW    32
#define KK    9
#define EPS   1e-8f
// GAIN = 1/sqrt(512*9)
#define GAIN  0.014731391274719738f

// Conv tiling
#define O_TILE   32
#define IC_TILE  8
#define ROWS     8
#define COLS     32

// Scratch (no cudaMalloc allowed)
__device__ float g_wsq[CIN * COUT];     // [i][o] transposed for coalesced sigma reads
__device__ float g_sigma[BATCH * COUT];

// ---------------------------------------------------------------------------
// Kernel A: wsq[i][o] = sum_k weight[o][i][k]^2
// ---------------------------------------------------------------------------
__global__ void wsq_kernel(const float* __restrict__ weight) {
    int idx = blockIdx.x * 256 + threadIdx.x;   // idx = o*512 + i
    if (idx < COUT * CIN) {
        const float* wp = weight + (size_t)idx * KK;
        float s = 0.f;
#pragma unroll
        for (int k = 0; k < KK; k++) s += wp[k] * wp[k];
        int o = idx >> 9;
        int i = idx & 511;
        g_wsq[i * COUT + o] = s;
    }
}

// ---------------------------------------------------------------------------
// Kernel B: sigma[b][o] = rsqrt(GAIN^2 * sum_i style[b][i]^2 * wsq[i][o] + eps)
// ---------------------------------------------------------------------------
__global__ void sigma_kernel(const float* __restrict__ style) {
    __shared__ float s2[CIN];
    int b = blockIdx.x;
    int o = threadIdx.x;   // 512 threads
    float sv = style[b * CIN + o];
    s2[o] = sv * sv;
    __syncthreads();
    float acc = 0.f;
#pragma unroll 8
    for (int i = 0; i < CIN; i++)
        acc = fmaf(s2[i], g_wsq[i * COUT + o], acc);
    g_sigma[b * COUT + o] = rsqrtf(GAIN * GAIN * acc + EPS);
}

// ---------------------------------------------------------------------------
// Kernel C: direct conv.
// Grid: (H/ROWS=4, COUT/O_TILE=16, BATCH=16). Block: 256 threads.
// Block computes out[b][oBase:oBase+32][rowBase:rowBase+8][0:32].
// Thread: 8 output channels x 4 pixels (32 accumulators).
// acc = sum_{i,kh,kw} (weight[o][i][kh][kw]*style[b][i]) * x[b][i][y+kh-1][x+kw-1]
// out = acc * GAIN * sigma[b][o]
// ---------------------------------------------------------------------------
__global__ __launch_bounds__(256, 2)
void conv_kernel(const float* __restrict__ x,
                 const float* __restrict__ style,
                 const float* __restrict__ weight,
                 float* __restrict__ out) {
    // x tile: IC_TILE channels, (ROWS+2) x (COLS+2) halo, stride 35 (conflict-free)
    __shared__ float sx[IC_TILE][ROWS + 2][35];
    // weights (style pre-applied): [ic][kk][o], row stride 36 (16B aligned rows)
    __shared__ float sw[IC_TILE][KK][36];

    const int b       = blockIdx.z;
    const int oBase   = blockIdx.y * O_TILE;
    const int rowBase = blockIdx.x * ROWS;
    const int tid     = threadIdx.x;

    const int q  = tid & 63;        // pixel quad 0..63
    const int og = tid >> 6;        // 0..3 (8 output channels each)
    const int r  = q >> 3;          // row within tile 0..7
    const int c0 = (q & 7) * 4;     // col base 0..28

    float acc[8][4];
#pragma unroll
    for (int jj = 0; jj < 8; jj++)
#pragma unroll
        for (int j = 0; j < 4; j++) acc[jj][j] = 0.f;

    const float* xb = x + (size_t)b * CIN * HW * HW;
    const float* stb = style + b * CIN;

    for (int icb = 0; icb < CIN; icb += IC_TILE) {
        __syncthreads();
        // ---- load x tile: 8 * 10 * 34 = 2720 elements ----
        for (int idx = tid; idx < IC_TILE * 10 * 34; idx += 256) {
            int ic  = idx / 340;
            int rem = idx - ic * 340;
            int lr  = rem / 34;
            int lc  = rem - lr * 34;
            int gy  = rowBase + lr - 1;
            int gx  = lc - 1;
            float v = 0.f;
            if ((unsigned)gy < 32u && (unsigned)gx < 32u)
                v = xb[((icb + ic) * HW + gy) * HW + gx];
            sx[ic][lr][lc] = v;
        }
        // ---- load weights (coalesced: 72 consecutive floats per o) ----
        for (int idx = tid; idx < O_TILE * IC_TILE * KK; idx += 256) {
            int o = idx / (IC_TILE * KK);         // 0..31
            int t = idx - o * (IC_TILE * KK);     // 0..71
            int ic = t / KK;
            int kk = t - ic * KK;
            float wv = weight[(size_t)((oBase + o) * CIN + icb) * KK + t];
            sw[ic][kk][o] = wv * stb[icb + ic];
        }
        __syncthreads();
        // ---- compute ----
#pragma unroll
        for (int ic = 0; ic < IC_TILE; ic++) {
#pragma unroll
            for (int kh = 0; kh < 3; kh++) {
                float xr[6];
#pragma unroll
                for (int j = 0; j < 6; j++) xr[j] = sx[ic][r + kh][c0 + j];
#pragma unroll
                for (int kw = 0; kw < 3; kw++) {
                    const float4 w0 = *(const float4*)&sw[ic][kh * 3 + kw][og * 8];
                    const float4 w1 = *(const float4*)&sw[ic][kh * 3 + kw][og * 8 + 4];
                    const float wv[8] = {w0.x, w0.y, w0.z, w0.w,
                                         w1.x, w1.y, w1.z, w1.w};
#pragma unroll
                    for (int jj = 0; jj < 8; jj++)
#pragma unroll
                        for (int j = 0; j < 4; j++)
                            acc[jj][j] = fmaf(wv[jj], xr[kw + j], acc[jj][j]);
                }
            }
        }
    }

    // ---- store: scale by GAIN * sigma[b][o], vectorized float4 ----
#pragma unroll
    for (int jj = 0; jj < 8; jj++) {
        int o = oBase + og * 8 + jj;
        float s = GAIN * g_sigma[b * COUT + o];
        float4 v;
        v.x = acc[jj][0] * s;
        v.y = acc[jj][1] * s;
        v.z = acc[jj][2] * s;
        v.w = acc[jj][3] * s;
        *(float4*)&out[(((size_t)b * COUT + o) * HW + rowBase + r) * HW + c0] = v;
    }
}

extern "C" void kernel_launch(void* const* d_in, const int* in_sizes, int n_in,
                              void* d_out, int out_size) {
    const float* x      = (const float*)d_in[0];  // [16,512,32,32]
    const float* style  = (const float*)d_in[1];  // [16,512]
    const float* weight = (const float*)d_in[2];  // [512,512,3,3]
    float* out = (float*)d_out;

    wsq_kernel<<<(COUT * CIN + 255) / 256, 256>>>(weight);
    sigma_kernel<<<BATCH, CIN>>>(style);

    dim3 grid(HW / ROWS, COUT / O_TILE, BATCH);  // (4, 16, 16)
    conv_kernel<<<grid, 256>>>(x, style, weight, out);
}

// round 4
// speedup vs baseline: 8.1724x; 8.1724x over previous
#include <cuda_runtime.h>
#include <cuda_fp16.h>
#include <cstdint>

#define BATCH 16
#define CIN   512
#define COUT  512
#define HW    32
#define EPS   1e-8f
#define GAIN  0.014731391274719738f   // 1/sqrt(512*9)

#define PW    34                      // padded width/height
#define PPIX  1156                    // 34*34
#define GUARD 64                      // guard rows each side of padded image
#define PROWS (PPIX + 2 * GUARD)      // 1284
#define KC    32                      // halfs of K per mainloop step
#define NSTEPS 144                    // 9 taps * 16 ic-chunks

// ---------------- device scratch (no cudaMalloc allowed) ----------------
__device__ float  g_wsq[CIN * COUT];                    // [i][o]
__device__ float  g_sigma[BATCH * COUT];                // [b][o]
__device__ __half g_xsh[(size_t)BATCH * PROWS * CIN];   // [b][64+p'][i] style-modulated, padded
__device__ __half g_w9h[9 * COUT * CIN];                // [tap][o][i]

// ---------------- PTX helpers (base ISA only: sm_80+, no 'a' features) ----
__device__ __forceinline__ uint32_t smem_u32(const void* p) {
    uint32_t a;
    asm("{ .reg .u64 t; cvta.to.shared.u64 t, %1; cvt.u32.u64 %0, t; }" : "=r"(a) : "l"(p));
    return a;
}
__device__ __forceinline__ void cpa16(uint32_t dst, const void* src) {
    asm volatile("cp.async.cg.shared.global [%0], [%1], 16;" :: "r"(dst), "l"(src));
}
#define CP_COMMIT()  asm volatile("cp.async.commit_group;" ::: "memory")
#define CP_WAIT(n)   asm volatile("cp.async.wait_group %0;" :: "n"(n) : "memory")

#define LDM_X4(r0, r1, r2, r3, a) \
    asm volatile("ldmatrix.sync.aligned.m8n8.x4.shared.b16 {%0,%1,%2,%3}, [%4];" \
        : "=r"(r0), "=r"(r1), "=r"(r2), "=r"(r3) : "r"(a))

#define MMA16816(c, a, b0, b1) \
    asm volatile("mma.sync.aligned.m16n8k16.row.col.f32.f16.f16.f32 " \
        "{%0,%1,%2,%3},{%4,%5,%6,%7},{%8,%9},{%0,%1,%2,%3};" \
        : "+f"((c)[0]), "+f"((c)[1]), "+f"((c)[2]), "+f"((c)[3]) \
        : "r"((a)[0]), "r"((a)[1]), "r"((a)[2]), "r"((a)[3]), "r"(b0), "r"(b1))

// ---------------- preprocessing ----------------
__global__ void wsq_kernel(const float* __restrict__ weight) {
    int idx = blockIdx.x * 256 + threadIdx.x;
    if (idx < COUT * CIN) {
        const float* wp = weight + (size_t)idx * 9;
        float s = 0.f;
#pragma unroll
        for (int k = 0; k < 9; k++) s += wp[k] * wp[k];
        g_wsq[(idx & 511) * COUT + (idx >> 9)] = s;
    }
}

__global__ void sigma_kernel(const float* __restrict__ style) {
    __shared__ float s2[CIN];
    int b = blockIdx.x, o = threadIdx.x;
    float sv = style[b * CIN + o];
    s2[o] = sv * sv;
    __syncthreads();
    float acc = 0.f;
#pragma unroll 8
    for (int i = 0; i < CIN; i++) acc = fmaf(s2[i], g_wsq[i * COUT + o], acc);
    g_sigma[b * COUT + o] = rsqrtf(GAIN * GAIN * acc + EPS);
}

__global__ void w9h_kernel(const float* __restrict__ weight) {
    int idx = blockIdx.x * 256 + threadIdx.x;   // o*512 + i
    if (idx < COUT * CIN) {
        const float* wp = weight + (size_t)idx * 9;
        int o = idx >> 9, i = idx & 511;
#pragma unroll
        for (int t = 0; t < 9; t++)
            g_w9h[(size_t)t * (COUT * CIN) + o * CIN + i] = __float2half_rn(wp[t]);
    }
}

// zero the guard bands (deterministic every launch)
__global__ void guard_kernel() {
    size_t idx = (size_t)blockIdx.x * 256 + threadIdx.x;  // uint32 writes
    const size_t per_b_u32 = 2 * GUARD * CIN / 2;         // 32768 uints per batch
    if (idx < (size_t)BATCH * per_b_u32) {
        int b = (int)(idx / per_b_u32);
        size_t r = (idx % per_b_u32) * 2;                 // half index inside guards
        size_t off = (r < (size_t)GUARD * CIN)
                       ? r
                       : (size_t)(GUARD + PPIX) * CIN + (r - (size_t)GUARD * CIN);
        *(uint32_t*)&g_xsh[(size_t)b * PROWS * CIN + off] = 0u;
    }
}

// g_xsh[b][64 + yp*34 + xp][i] = half(style[b][i] * x[b][i][yp-1][xp-1]); 0 on borders
__global__ void xsh_kernel(const float* __restrict__ x, const float* __restrict__ style) {
    __shared__ float tile[32][33];
    __shared__ float sstyle[32];
    int yp = blockIdx.x;   // 0..33
    int b = blockIdx.y;
    int tid = threadIdx.x;
    int lane = tid & 31, w = tid >> 5;
    bool border = (yp == 0) | (yp == 33);
    int y = yp - 1;
    for (int i0 = 0; i0 < CIN; i0 += 32) {
        __syncthreads();
        if (!border) {
            for (int k = tid; k < 1024; k += 256) {
                int ii = k >> 5, xx = k & 31;
                tile[ii][xx] = x[(((size_t)b * CIN + i0 + ii) * HW + y) * HW + xx];
            }
            if (tid < 32) sstyle[tid] = style[b * CIN + i0 + tid];
        }
        __syncthreads();
        for (int xp = w; xp < PW; xp += 8) {
            float v = 0.f;
            if (!border && xp >= 1 && xp <= 32)
                v = tile[lane][xp - 1] * sstyle[lane];
            g_xsh[((size_t)b * PROWS + GUARD + yp * PW + xp) * CIN + i0 + lane] = __float2half_rn(v);
        }
    }
}

// ---------------- main GEMM kernel: mma.sync fp16 ----------------
// Grid (9 px-tiles, 4 o-tiles, 16 b). CTA: 256 thr = 8 warps (2x4).
// CTA tile: M=128 (o), N=128 (padded pixels), K=4608 in 144 steps of 32.
// Warp tile 64x32: 4x4 m16n8 subtiles, 2 k16 steps per iter.
#define SROW 40          // smem row pitch in halfs (80 B) -> conflict-free ldmatrix
#define BUFB (128 * SROW * 2)   // 10240 bytes per buffer

__global__ __launch_bounds__(256, 2)
void mma_kernel(float* __restrict__ out) {
    __shared__ __align__(16) __half sA[2][128][SROW];
    __shared__ __align__(16) __half sB[2][128][SROW];

    const int tid  = threadIdx.x;
    const int wid  = tid >> 5, lane = tid & 31;
    const int m0   = (wid >> 2) * 64;      // warp M origin
    const int n0   = (wid & 3) * 32;       // warp N origin
    const int Pbase = blockIdx.x * 128;    // padded-pixel tile origin
    const int oBase = blockIdx.y * 128;
    const int b     = blockIdx.z;

    const uint32_t sAu = smem_u32(sA);
    const uint32_t sBu = smem_u32(sB);

    // per-thread ldmatrix address components
    const int rA = ((lane >> 3) & 1) * 8 + (lane & 7);
    const int kA = (lane >> 4) * 16;                   // bytes
    const int rB = (lane >> 4) * 8 + (lane & 7);
    const int kB = ((lane >> 3) & 1) * 16;             // bytes
    const uint32_t aAddr0 = sAu + (uint32_t)(m0 + rA) * (SROW * 2) + kA;
    const uint32_t bAddr0 = sBu + (uint32_t)(n0 + rB) * (SROW * 2) + kB;

    // staging source bases
    const __half* xsb = g_xsh + ((size_t)b * PROWS + GUARD + Pbase) * CIN;

    float c[4][4][4];
#pragma unroll
    for (int mi = 0; mi < 4; mi++)
#pragma unroll
        for (int ni = 0; ni < 4; ni++)
#pragma unroll
            for (int j = 0; j < 4; j++) c[mi][ni][j] = 0.f;

    const int sr = tid >> 2;          // staging row (64 rows per pass, 2 passes)
    const int sc = tid & 3;           // staging 16B chunk
    const uint32_t dstA0 = sAu + (uint32_t)sr * (SROW * 2) + sc * 16;
    const uint32_t dstB0 = sBu + (uint32_t)sr * (SROW * 2) + sc * 16;

    // stage step s into buffer buf
    auto stage = [&](int s, int buf) {
        const int icb = (s / 9) * KC;
        const int tap = s - (s / 9) * 9;
        const int dlt = (tap / 3 - 1) * PW + (tap % 3 - 1);
        const __half* Asrc = g_w9h + (size_t)tap * (COUT * CIN) + (size_t)oBase * CIN + icb;
        const __half* Bsrc = xsb + (size_t)dlt * CIN + icb;
        const uint32_t bo = (uint32_t)buf * BUFB;
#pragma unroll
        for (int h = 0; h < 2; h++) {
            int r = sr + h * 64;
            cpa16(dstA0 + bo + h * 64 * (SROW * 2), Asrc + (size_t)r * CIN + sc * 8);
            cpa16(dstB0 + bo + h * 64 * (SROW * 2), Bsrc + (size_t)r * CIN + sc * 8);
        }
    };

    stage(0, 0);
    CP_COMMIT();

    for (int s = 0; s < NSTEPS; s++) {
        const int buf = s & 1;
        if (s + 1 < NSTEPS) {
            stage(s + 1, buf ^ 1);
            CP_COMMIT();
            CP_WAIT(1);
        } else {
            CP_WAIT(0);
        }
        __syncthreads();

        const uint32_t aB = aAddr0 + (uint32_t)buf * BUFB;
        const uint32_t bBu2 = bAddr0 + (uint32_t)buf * BUFB;
#pragma unroll
        for (int kt = 0; kt < 2; kt++) {
            uint32_t a[4][4], bb[4][2];
#pragma unroll
            for (int mi = 0; mi < 4; mi++)
                LDM_X4(a[mi][0], a[mi][1], a[mi][2], a[mi][3],
                       aB + (uint32_t)mi * 16 * (SROW * 2) + kt * 32);
#pragma unroll
            for (int np = 0; np < 2; np++)
                LDM_X4(bb[np * 2][0], bb[np * 2][1], bb[np * 2 + 1][0], bb[np * 2 + 1][1],
                       bBu2 + (uint32_t)np * 16 * (SROW * 2) + kt * 32);
#pragma unroll
            for (int mi = 0; mi < 4; mi++)
#pragma unroll
                for (int ni = 0; ni < 4; ni++)
                    MMA16816(c[mi][ni], a[mi], bb[ni][0], bb[ni][1]);
        }
        __syncthreads();
    }

    // ---- epilogue: scale by GAIN*sigma, store valid pixels ----
    const int g  = lane >> 2;
    const int t4 = lane & 3;
#pragma unroll
    for (int mi = 0; mi < 4; mi++) {
        const int oL = oBase + m0 + mi * 16 + g;
        const float sL = GAIN * g_sigma[b * COUT + oL];
        const float sH = GAIN * g_sigma[b * COUT + oL + 8];
#pragma unroll
        for (int ni = 0; ni < 4; ni++) {
            const int P0 = Pbase + n0 + ni * 8 + 2 * t4;
#pragma unroll
            for (int j = 0; j < 2; j++) {
                const int P  = P0 + j;
                const int yp = P / PW, xp = P - (P / PW) * PW;
                if ((unsigned)(xp - 1) < 32u && (unsigned)(yp - 1) < 32u) {
                    const size_t base = (((size_t)b * COUT) * HW + (yp - 1)) * HW + (xp - 1);
                    out[base + (size_t)oL * HW * HW]       = c[mi][ni][j]     * sL;
                    out[base + (size_t)(oL + 8) * HW * HW] = c[mi][ni][2 + j] * sH;
                }
            }
        }
    }
}

// ---------------- launch ----------------
extern "C" void kernel_launch(void* const* d_in, const int* in_sizes, int n_in,
                              void* d_out, int out_size) {
    const float* x      = (const float*)d_in[0];
    const float* style  = (const float*)d_in[1];
    const float* weight = (const float*)d_in[2];
    float* out = (float*)d_out;

    wsq_kernel<<<(COUT * CIN + 255) / 256, 256>>>(weight);
    sigma_kernel<<<BATCH, CIN>>>(style);
    w9h_kernel<<<(COUT * CIN + 255) / 256, 256>>>(weight);
    guard_kernel<<<(BATCH * 2 * GUARD * CIN / 2 + 255) / 256, 256>>>();
    xsh_kernel<<<dim3(PW, BATCH), 256>>>(x, style);

    mma_kernel<<<dim3(9, 4, BATCH), 256>>>(out);
}

// round 5
// speedup vs baseline: 9.2334x; 1.1298x over previous
#include <cuda_runtime.h>
#include <cuda_fp16.h>
#include <cstdint>

#define BATCH 16
#define CIN   512
#define COUT  512
#define HW    32
#define EPS   1e-8f
#define GAIN  0.014731391274719738f   // 1/sqrt(512*9)

#define PW    34                      // padded width/height
#define PPIX  1156                    // 34*34
#define GUARD 64                      // guard rows each side of padded image
#define PROWS (PPIX + 2 * GUARD)      // 1284
#define KC    64                      // halfs of K per mainloop step
#define NSTEPS 72                     // 9 taps * 8 ic-chunks

// ---------------- device scratch (no cudaMalloc allowed) ----------------
__device__ float  g_wsq[CIN * COUT];                    // [i][o]
__device__ float  g_sigma[BATCH * COUT];                // [b][o]
__device__ __half g_xsh[(size_t)BATCH * PROWS * CIN];   // [b][64+p'][i] style-modulated, padded
__device__ __half g_w9h[9 * COUT * CIN];                // [tap][o][i]

// ---------------- PTX helpers (base ISA only) ----------------
__device__ __forceinline__ uint32_t smem_u32(const void* p) {
    uint32_t a;
    asm("{ .reg .u64 t; cvta.to.shared.u64 t, %1; cvt.u32.u64 %0, t; }" : "=r"(a) : "l"(p));
    return a;
}
__device__ __forceinline__ void cpa16(uint32_t dst, const void* src) {
    asm volatile("cp.async.cg.shared.global [%0], [%1], 16;" :: "r"(dst), "l"(src));
}
#define CP_COMMIT()  asm volatile("cp.async.commit_group;" ::: "memory")
#define CP_WAIT(n)   asm volatile("cp.async.wait_group %0;" :: "n"(n) : "memory")

#define LDM_X4(r0, r1, r2, r3, a) \
    asm volatile("ldmatrix.sync.aligned.m8n8.x4.shared.b16 {%0,%1,%2,%3}, [%4];" \
        : "=r"(r0), "=r"(r1), "=r"(r2), "=r"(r3) : "r"(a))

#define MMA16816(c, a, b0, b1) \
    asm volatile("mma.sync.aligned.m16n8k16.row.col.f32.f16.f16.f32 " \
        "{%0,%1,%2,%3},{%4,%5,%6,%7},{%8,%9},{%0,%1,%2,%3};" \
        : "+f"((c)[0]), "+f"((c)[1]), "+f"((c)[2]), "+f"((c)[3]) \
        : "r"((a)[0]), "r"((a)[1]), "r"((a)[2]), "r"((a)[3]), "r"(b0), "r"(b1))

// ---------------- preprocessing ----------------
// fused: per (o,i) -> wsq (transposed) + 9 tap halfs
__global__ void wprep_kernel(const float* __restrict__ weight) {
    int idx = blockIdx.x * 256 + threadIdx.x;   // o*512 + i
    if (idx < COUT * CIN) {
        const float* wp = weight + (size_t)idx * 9;
        int o = idx >> 9, i = idx & 511;
        float s = 0.f;
#pragma unroll
        for (int t = 0; t < 9; t++) {
            float w = wp[t];
            s += w * w;
            g_w9h[(size_t)t * (COUT * CIN) + o * CIN + i] = __float2half_rn(w);
        }
        g_wsq[i * COUT + o] = s;
    }
}

__global__ void sigma_kernel(const float* __restrict__ style) {
    __shared__ float s2[CIN];
    int b = blockIdx.x, o = threadIdx.x;
    float sv = style[b * CIN + o];
    s2[o] = sv * sv;
    __syncthreads();
    float acc = 0.f;
#pragma unroll 8
    for (int i = 0; i < CIN; i++) acc = fmaf(s2[i], g_wsq[i * COUT + o], acc);
    g_sigma[b * COUT + o] = rsqrtf(GAIN * GAIN * acc + EPS);
}

// zero the guard bands
__global__ void guard_kernel() {
    size_t idx = (size_t)blockIdx.x * 256 + threadIdx.x;
    const size_t per_b_u32 = 2 * GUARD * CIN / 2;
    if (idx < (size_t)BATCH * per_b_u32) {
        int b = (int)(idx / per_b_u32);
        size_t r = (idx % per_b_u32) * 2;
        size_t off = (r < (size_t)GUARD * CIN)
                       ? r
                       : (size_t)(GUARD + PPIX) * CIN + (r - (size_t)GUARD * CIN);
        *(uint32_t*)&g_xsh[(size_t)b * PROWS * CIN + off] = 0u;
    }
}

// g_xsh[b][64 + yp*34 + xp][i] = half(style[b][i] * x[b][i][yp-1][xp-1]); 0 on borders
__global__ void xsh_kernel(const float* __restrict__ x, const float* __restrict__ style) {
    __shared__ float tile[32][33];
    __shared__ float sstyle[32];
    int yp = blockIdx.x;   // 0..33
    int b = blockIdx.y;
    int tid = threadIdx.x;
    int lane = tid & 31, w = tid >> 5;
    bool border = (yp == 0) | (yp == 33);
    int y = yp - 1;
    for (int i0 = 0; i0 < CIN; i0 += 32) {
        __syncthreads();
        if (!border) {
            for (int k = tid; k < 1024; k += 256) {
                int ii = k >> 5, xx = k & 31;
                tile[ii][xx] = x[(((size_t)b * CIN + i0 + ii) * HW + y) * HW + xx];
            }
            if (tid < 32) sstyle[tid] = style[b * CIN + i0 + tid];
        }
        __syncthreads();
        for (int xp = w; xp < PW; xp += 8) {
            float v = 0.f;
            if (!border && xp >= 1 && xp <= 32)
                v = tile[lane][xp - 1] * sstyle[lane];
            g_xsh[((size_t)b * PROWS + GUARD + yp * PW + xp) * CIN + i0 + lane] = __float2half_rn(v);
        }
    }
}

// ---------------- main GEMM kernel: mma.sync fp16, 3-stage cp.async ----------------
// Grid (9 px-tiles, 4 o-tiles, 16 b). CTA 256 thr = 8 warps (2x4).
// CTA tile M=128 (o), N=128 (padded pixels), K=4608 in 72 steps of 64.
#define SROWB 144                 // smem row pitch bytes (128B data + 16B pad)
#define TILEB (128 * SROWB)       // 18432 B per stage per operand
#define NSTG  3
#define SM_TOTAL (2 * NSTG * TILEB)   // 110592

__global__ __launch_bounds__(256, 2)
void mma_kernel(float* __restrict__ out) {
    extern __shared__ __align__(16) char smem[];
    const uint32_t sAu = smem_u32(smem);
    const uint32_t sBu = sAu + NSTG * TILEB;

    const int tid  = threadIdx.x;
    const int wid  = tid >> 5, lane = tid & 31;
    const int m0   = (wid >> 2) * 64;      // warp M origin
    const int n0   = (wid & 3) * 32;       // warp N origin
    const int Pbase = blockIdx.x * 128;
    const int oBase = blockIdx.y * 128;
    const int b     = blockIdx.z;

    // ldmatrix per-thread address components (validated in R4)
    const int rA = ((lane >> 3) & 1) * 8 + (lane & 7);
    const int kA = (lane >> 4) * 16;                   // bytes
    const int rB = (lane >> 4) * 8 + (lane & 7);
    const int kB = ((lane >> 3) & 1) * 16;             // bytes
    const uint32_t aAddr0 = sAu + (uint32_t)(m0 + rA) * SROWB + kA;
    const uint32_t bAddr0 = sBu + (uint32_t)(n0 + rB) * SROWB + kB;

    const __half* xsb = g_xsh + ((size_t)b * PROWS + GUARD + Pbase) * CIN;

    float c[4][4][4];
#pragma unroll
    for (int mi = 0; mi < 4; mi++)
#pragma unroll
        for (int ni = 0; ni < 4; ni++)
#pragma unroll
            for (int j = 0; j < 4; j++) c[mi][ni][j] = 0.f;

    // staging: thread -> (row block, 16B chunk); 4 passes of 32 rows
    const int sr = tid >> 3;          // 0..31
    const int sc = tid & 7;           // 0..7
    const uint32_t dstA0 = sAu + (uint32_t)sr * SROWB + sc * 16;
    const uint32_t dstB0 = sBu + (uint32_t)sr * SROWB + sc * 16;

    auto stage = [&](int s) {
        const int buf = s % NSTG;
        const int icb = (s / 9) * KC;
        const int tap = s - (s / 9) * 9;
        const int dlt = (tap / 3 - 1) * PW + (tap % 3 - 1);
        const __half* Asrc = g_w9h + (size_t)tap * (COUT * CIN) + (size_t)oBase * CIN + icb;
        const __half* Bsrc = xsb + (size_t)dlt * CIN + icb;
        const uint32_t bo = (uint32_t)buf * TILEB;
#pragma unroll
        for (int h = 0; h < 4; h++) {
            const int r = sr + h * 32;
            cpa16(dstA0 + bo + (uint32_t)h * 32 * SROWB, Asrc + (size_t)r * CIN + sc * 8);
            cpa16(dstB0 + bo + (uint32_t)h * 32 * SROWB, Bsrc + (size_t)r * CIN + sc * 8);
        }
        CP_COMMIT();
    };

    stage(0);
    stage(1);

    for (int s = 0; s < NSTEPS; s++) {
        if (s == NSTEPS - 1) { CP_WAIT(0); } else { CP_WAIT(1); }
        __syncthreads();                       // single barrier per step
        if (s + 2 < NSTEPS) stage(s + 2);      // after sync: no race vs compute(s-1)

        const uint32_t bo = (uint32_t)(s % NSTG) * TILEB;
        const uint32_t aB = aAddr0 + bo;
        const uint32_t bB = bAddr0 + bo;
#pragma unroll
        for (int kt = 0; kt < 4; kt++) {
            uint32_t a[4][4], bb[4][2];
#pragma unroll
            for (int mi = 0; mi < 4; mi++)
                LDM_X4(a[mi][0], a[mi][1], a[mi][2], a[mi][3],
                       aB + (uint32_t)mi * 16 * SROWB + kt * 32);
#pragma unroll
            for (int np = 0; np < 2; np++)
                LDM_X4(bb[np * 2][0], bb[np * 2][1], bb[np * 2 + 1][0], bb[np * 2 + 1][1],
                       bB + (uint32_t)np * 16 * SROWB + kt * 32);
#pragma unroll
            for (int mi = 0; mi < 4; mi++)
#pragma unroll
                for (int ni = 0; ni < 4; ni++)
                    MMA16816(c[mi][ni], a[mi], bb[ni][0], bb[ni][1]);
        }
    }

    // ---- epilogue: scale by GAIN*sigma, store valid pixels ----
    const int g  = lane >> 2;
    const int t4 = lane & 3;
#pragma unroll
    for (int mi = 0; mi < 4; mi++) {
        const int oL = oBase + m0 + mi * 16 + g;
        const float sL = GAIN * g_sigma[b * COUT + oL];
        const float sH = GAIN * g_sigma[b * COUT + oL + 8];
#pragma unroll
        for (int ni = 0; ni < 4; ni++) {
            const int P0 = Pbase + n0 + ni * 8 + 2 * t4;
#pragma unroll
            for (int j = 0; j < 2; j++) {
                const int P  = P0 + j;
                const int yp = P / PW, xp = P - (P / PW) * PW;
                if ((unsigned)(xp - 1) < 32u && (unsigned)(yp - 1) < 32u) {
                    const size_t base = (((size_t)b * COUT) * HW + (yp - 1)) * HW + (xp - 1);
                    out[base + (size_t)oL * HW * HW]       = c[mi][ni][j]     * sL;
                    out[base + (size_t)(oL + 8) * HW * HW] = c[mi][ni][2 + j] * sH;
                }
            }
        }
    }
}

// ---------------- launch ----------------
extern "C" void kernel_launch(void* const* d_in, const int* in_sizes, int n_in,
                              void* d_out, int out_size) {
    const float* x      = (const float*)d_in[0];
    const float* style  = (const float*)d_in[1];
    const float* weight = (const float*)d_in[2];
    float* out = (float*)d_out;

    wprep_kernel<<<(COUT * CIN + 255) / 256, 256>>>(weight);
    sigma_kernel<<<BATCH, CIN>>>(style);
    guard_kernel<<<(BATCH * 2 * GUARD * CIN / 2 + 255) / 256, 256>>>();
    xsh_kernel<<<dim3(PW, BATCH), 256>>>(x, style);

    static int smem_set = 0;
    if (!smem_set) {
        cudaFuncSetAttribute(mma_kernel, cudaFuncAttributeMaxDynamicSharedMemorySize, SM_TOTAL);
        smem_set = 1;
    }
    mma_kernel<<<dim3(9, 4, BATCH), 256, SM_TOTAL>>>(out);
}

// round 6
// speedup vs baseline: 11.0805x; 1.2000x over previous
#include <cuda_runtime.h>
#include <cuda_fp16.h>
#include <cstdint>

#define BATCH 16
#define CIN   512
#define COUT  512
#define HW    32
#define EPS   1e-8f
#define GAIN  0.014731391274719738f   // 1/sqrt(512*9)

#define PW    34
#define PPIX  1156
#define GUARD 64
#define PROWS (PPIX + 2 * GUARD)      // 1284
#define KC    64                      // halfs of K per step
#define TAPS  9
#define NCHUNK 8
#define NSTEPS 72                     // TAPS * NCHUNK

// ---------------- device scratch ----------------
__device__ float  g_wsq[CIN * COUT];                    // [i][o]
__device__ float  g_sigma[BATCH * COUT];                // [b][o]
__device__ __half g_xsh[(size_t)BATCH * PROWS * CIN];   // [b][GUARD+p'][i]
__device__ __half g_w9h[9 * COUT * CIN];                // [tap][o][i]

// ---------------- PTX helpers ----------------
__device__ __forceinline__ uint32_t smem_u32(const void* p) {
    uint32_t a;
    asm("{ .reg .u64 t; cvta.to.shared.u64 t, %1; cvt.u32.u64 %0, t; }" : "=r"(a) : "l"(p));
    return a;
}
__device__ __forceinline__ void cpa16(uint32_t dst, const void* src) {
    asm volatile("cp.async.cg.shared.global [%0], [%1], 16;" :: "r"(dst), "l"(src));
}
#define CP_COMMIT()  asm volatile("cp.async.commit_group;" ::: "memory")
#define CP_WAIT(n)   asm volatile("cp.async.wait_group %0;" :: "n"(n) : "memory")

#define LDM_X4(r0, r1, r2, r3, a) \
    asm volatile("ldmatrix.sync.aligned.m8n8.x4.shared.b16 {%0,%1,%2,%3}, [%4];" \
        : "=r"(r0), "=r"(r1), "=r"(r2), "=r"(r3) : "r"(a))

#define MMA16816(c, a, b0, b1) \
    asm volatile("mma.sync.aligned.m16n8k16.row.col.f32.f16.f16.f32 " \
        "{%0,%1,%2,%3},{%4,%5,%6,%7},{%8,%9},{%0,%1,%2,%3};" \
        : "+f"((c)[0]), "+f"((c)[1]), "+f"((c)[2]), "+f"((c)[3]) \
        : "r"((a)[0]), "r"((a)[1]), "r"((a)[2]), "r"((a)[3]), "r"(b0), "r"(b1))

// ---------------- preprocessing 1: wsq + w9h ----------------
__global__ void wprep_kernel(const float* __restrict__ weight) {
    int idx = blockIdx.x * 256 + threadIdx.x;   // o*512 + i
    if (idx < COUT * CIN) {
        const float* wp = weight + (size_t)idx * 9;
        int o = idx >> 9, i = idx & 511;
        float s = 0.f;
#pragma unroll
        for (int t = 0; t < 9; t++) {
            float w = wp[t];
            s += w * w;
            g_w9h[(size_t)t * (COUT * CIN) + o * CIN + i] = __float2half_rn(w);
        }
        g_wsq[i * COUT + o] = s;
    }
}

// ---------------- preprocessing 2: fused guard + modulate + sigma ----------
// grid (PW+2, BATCH), 256 threads.
//  bx in [0,34): one padded row yp=bx (zero if border, else modulated half2 writes)
//  bx == 34: zero guard bands for batch b
//  bx == 35: sigma[b][*]
__global__ void xsh2_kernel(const float* __restrict__ x, const float* __restrict__ style) {
    const int b   = blockIdx.y;
    const int bx  = blockIdx.x;
    const int tid = threadIdx.x;

    if (bx == PW) {          // guard bands: rows [0,GUARD) and [GUARD+PPIX, PROWS)
        uint4 z = make_uint4(0, 0, 0, 0);
        uint4* base = (uint4*)&g_xsh[(size_t)b * PROWS * CIN];
        const int per_band = GUARD * CIN / 8;          // uint4 count = 4096
        for (int k = tid; k < per_band; k += 256) {
            base[k] = z;
            base[(GUARD + PPIX) * CIN / 8 + k] = z;
        }
        return;
    }
    if (bx == PW + 1) {      // sigma
        __shared__ float s2[CIN];
        for (int i = tid; i < CIN; i += 256) {
            float sv = style[b * CIN + i];
            s2[i] = sv * sv;
        }
        __syncthreads();
#pragma unroll
        for (int h = 0; h < 2; h++) {
            int o = tid + h * 256;
            float acc = 0.f;
#pragma unroll 8
            for (int i = 0; i < CIN; i++) acc = fmaf(s2[i], g_wsq[i * COUT + o], acc);
            g_sigma[b * COUT + o] = rsqrtf(GAIN * GAIN * acc + EPS);
        }
        return;
    }

    const int yp = bx;
    __half* rowbase = &g_xsh[((size_t)b * PROWS + GUARD + (size_t)yp * PW) * CIN];

    if (yp == 0 || yp == PW - 1) {   // border row: all zero (34*512 halfs)
        uint4 z = make_uint4(0, 0, 0, 0);
        uint4* p = (uint4*)rowbase;
        for (int k = tid; k < PW * CIN / 8; k += 256) p[k] = z;
        return;
    }

    __shared__ float tE[32][33], tO[32][33];   // [xx][pair]
    __shared__ float sst[64];
    const int y = yp - 1;
    const int lane = tid & 31, w = tid >> 5;

    for (int i0 = 0; i0 < CIN; i0 += 64) {
        __syncthreads();
        for (int k = tid; k < 2048; k += 256) {
            int ch = k >> 5, xx = k & 31;
            float v = x[(((size_t)b * CIN + i0 + ch) * HW + y) * HW + xx];
            if (ch & 1) tO[xx][ch >> 1] = v;
            else        tE[xx][ch >> 1] = v;
        }
        if (tid < 64) sst[tid] = style[b * CIN + i0 + tid];
        __syncthreads();
        for (int xp = w; xp < PW; xp += 8) {
            __half2 h2;
            if (xp == 0 || xp == PW - 1) {
                h2 = __floats2half2_rn(0.f, 0.f);
            } else {
                float v0 = tE[xp - 1][lane] * sst[2 * lane];
                float v1 = tO[xp - 1][lane] * sst[2 * lane + 1];
                h2 = __floats2half2_rn(v0, v1);
            }
            *(__half2*)&rowbase[(size_t)xp * CIN + i0 + 2 * lane] = h2;
        }
    }
}

// ---------------- main GEMM kernel ----------------
// CTA 128x128, K=4608 in 72 steps of 64. A: 3-stage ring per step.
// B: ONE 198-row window per ic-chunk, shared by all 9 taps (2 buffers).
#define SROWB 144
#define ATILE (128 * SROWB)        // 18432
#define BROWS 198
#define BTILE (BROWS * SROWB)      // 28512
#define SM_TOTAL (3 * ATILE + 2 * BTILE)   // 112320

__global__ __launch_bounds__(256, 2)
void mma_kernel(float* __restrict__ out) {
    extern __shared__ __align__(16) char smem[];
    const uint32_t sAu = smem_u32(smem);
    const uint32_t sBu = sAu + 3 * ATILE;

    const int tid  = threadIdx.x;
    const int wid  = tid >> 5, lane = tid & 31;
    const int m0   = (wid >> 2) * 64;
    const int n0   = (wid & 3) * 32;
    const int Pbase = blockIdx.x * 128;
    const int oBase = blockIdx.y * 128;
    const int b     = blockIdx.z;

    const int rA = ((lane >> 3) & 1) * 8 + (lane & 7);
    const int kA = (lane >> 4) * 16;
    const int rB = (lane >> 4) * 8 + (lane & 7);
    const int kB = ((lane >> 3) & 1) * 16;
    const uint32_t aAddr0 = sAu + (uint32_t)(m0 + rA) * SROWB + kA;
    const uint32_t bAddr0 = sBu + (uint32_t)(n0 + rB) * SROWB + kB;

    // B window base in gmem: row r of window = padded pixel Pbase - 35 + r
    const __half* bwin = g_xsh + ((size_t)b * PROWS + GUARD + Pbase - 35) * CIN;

    float c[4][4][4];
#pragma unroll
    for (int mi = 0; mi < 4; mi++)
#pragma unroll
        for (int ni = 0; ni < 4; ni++)
#pragma unroll
            for (int j = 0; j < 4; j++) c[mi][ni][j] = 0.f;

    const int sr = tid >> 3;          // 0..31
    const int sc = tid & 7;           // 0..7
    const uint32_t dstA0 = sAu + (uint32_t)sr * SROWB + sc * 16;

    auto stageA = [&](int s2) {
        const int k2 = s2 / TAPS, t2 = s2 - k2 * TAPS;
        const __half* Asrc = g_w9h + (size_t)t2 * (COUT * CIN) + (size_t)oBase * CIN + k2 * KC;
        const uint32_t bo = (uint32_t)(s2 % 3) * ATILE;
#pragma unroll
        for (int h = 0; h < 4; h++) {
            const int r = sr + h * 32;
            cpa16(dstA0 + bo + (uint32_t)h * 32 * SROWB, Asrc + (size_t)r * CIN + sc * 8);
        }
    };
    // stage one 25-row piece (t in 0..7) of chunk kN's B window
    auto stageBp = [&](int kN, int t) {
        const int r0 = t * 25;
        const int n  = (r0 + 25 <= BROWS) ? 25 : (BROWS - r0);
        const int r  = sr;            // 0..31
        if (r < n) {
            const __half* src = bwin + (size_t)(r0 + r) * CIN + kN * KC + sc * 8;
            cpa16(sBu + (uint32_t)(kN & 1) * BTILE + (uint32_t)(r0 + r) * SROWB + sc * 16, src);
        }
    };

    // prologue: g0 = {A(0), full B(0)}, g1 = {A(1)}
    stageA(0);
    for (int r = sr; r < BROWS; r += 32)
        cpa16(sBu + (uint32_t)r * SROWB + sc * 16, bwin + (size_t)r * CIN + sc * 8);
    CP_COMMIT();
    stageA(1);
    CP_COMMIT();

    for (int s = 0; s < NSTEPS; s++) {
        const int k = s / TAPS, t = s - k * TAPS;
        if (s == NSTEPS - 1) { CP_WAIT(0); } else { CP_WAIT(1); }
        __syncthreads();
        if (s + 2 < NSTEPS) stageA(s + 2);
        if (t < 8 && k + 1 < NCHUNK) stageBp(k + 1, t);
        CP_COMMIT();

        const int dlt = (t / 3 - 1) * PW + (t % 3 - 1);
        const uint32_t aB = aAddr0 + (uint32_t)(s % 3) * ATILE;
        const uint32_t bB = bAddr0 + (uint32_t)(k & 1) * BTILE + (uint32_t)(dlt + 35) * SROWB;
#pragma unroll
        for (int kt = 0; kt < 4; kt++) {
            uint32_t a[4][4], bb[4][2];
#pragma unroll
            for (int mi = 0; mi < 4; mi++)
                LDM_X4(a[mi][0], a[mi][1], a[mi][2], a[mi][3],
                       aB + (uint32_t)mi * 16 * SROWB + kt * 32);
#pragma unroll
            for (int np = 0; np < 2; np++)
                LDM_X4(bb[np * 2][0], bb[np * 2][1], bb[np * 2 + 1][0], bb[np * 2 + 1][1],
                       bB + (uint32_t)np * 16 * SROWB + kt * 32);
#pragma unroll
            for (int mi = 0; mi < 4; mi++)
#pragma unroll
                for (int ni = 0; ni < 4; ni++)
                    MMA16816(c[mi][ni], a[mi], bb[ni][0], bb[ni][1]);
        }
    }

    // ---- epilogue ----
    const int g  = lane >> 2;
    const int t4 = lane & 3;
#pragma unroll
    for (int mi = 0; mi < 4; mi++) {
        const int oL = oBase + m0 + mi * 16 + g;
        const float sL = GAIN * g_sigma[b * COUT + oL];
        const float sH = GAIN * g_sigma[b * COUT + oL + 8];
#pragma unroll
        for (int ni = 0; ni < 4; ni++) {
            const int P0 = Pbase + n0 + ni * 8 + 2 * t4;
#pragma unroll
            for (int j = 0; j < 2; j++) {
                const int P  = P0 + j;
                const int yp = P / PW, xp = P - (P / PW) * PW;
                if ((unsigned)(xp - 1) < 32u && (unsigned)(yp - 1) < 32u) {
                    const size_t base = (((size_t)b * COUT) * HW + (yp - 1)) * HW + (xp - 1);
                    out[base + (size_t)oL * HW * HW]       = c[mi][ni][j]     * sL;
                    out[base + (size_t)(oL + 8) * HW * HW] = c[mi][ni][2 + j] * sH;
                }
            }
        }
    }
}

// ---------------- launch ----------------
extern "C" void kernel_launch(void* const* d_in, const int* in_sizes, int n_in,
                              void* d_out, int out_size) {
    const float* x      = (const float*)d_in[0];
    const float* style  = (const float*)d_in[1];
    const float* weight = (const float*)d_in[2];
    float* out = (float*)d_out;

    wprep_kernel<<<(COUT * CIN + 255) / 256, 256>>>(weight);
    xsh2_kernel<<<dim3(PW + 2, BATCH), 256>>>(x, style);

    static int smem_set = 0;
    if (!smem_set) {
        cudaFuncSetAttribute(mma_kernel, cudaFuncAttributeMaxDynamicSharedMemorySize, SM_TOTAL);
        smem_set = 1;
    }
    mma_kernel<<<dim3(9, 4, BATCH), 256, SM_TOTAL>>>(out);
}